// round 1
// baseline (speedup 1.0000x reference)
#include <cuda_runtime.h>
#include <math.h>

#define NN   10000
#define EE   160000
#define SEQL 96
#define HIDC 128
#define NH   8
#define HC   1024   // NH*HIDC
#define OUTC 768

// ---------------- scratch (device globals; no allocation allowed) ----------
__device__ float g_hw [NN * HC];   // W-transformed features (message source)
__device__ float g_agg[NN * HC];   // aggregation target
__device__ float g_hin[NN * HC];   // layer input (after relu+bias)
__device__ float g_asrc[NN * NH];
__device__ float g_adst[NN * NH];
__device__ float g_amax[NN * NH];
__device__ float g_den [NN * NH];
__device__ float g_ex  [EE * NH];  // logits, then exp values
__device__ float g_ce  [NH];

// ---------------- GEMM: C[M,Ncol] = A @ B, 64x64 tile, 4x4 micro ----------
// TA=false: A[m,k] = A[m*lda + k]   (row major, lda = K)
// TA=true : A[m,k] = A[k*lda + m]   (column major view, lda = M stride = NN)
template <bool TA>
__global__ void gemm64(const float* __restrict__ A, const float* __restrict__ B,
                       float* __restrict__ C, int M, int K, int Ncol, int lda)
{
    __shared__ float As[16][64];
    __shared__ float Bs[16][64];
    const int tid = threadIdx.x;
    const int tx = tid & 15, ty = tid >> 4;
    const int m0 = blockIdx.y * 64, n0 = blockIdx.x * 64;

    float acc[4][4] = {};

    for (int k0 = 0; k0 < K; k0 += 16) {
        if (TA) {
            const int ml = (tid & 15) * 4;
            const int kl = tid >> 4;
            const int m  = m0 + ml;
            float4 a;
            if (m + 3 < M) {
                a = *(const float4*)&A[(size_t)(k0 + kl) * lda + m];
            } else {
                a.x = (m + 0 < M) ? A[(size_t)(k0 + kl) * lda + m + 0] : 0.f;
                a.y = (m + 1 < M) ? A[(size_t)(k0 + kl) * lda + m + 1] : 0.f;
                a.z = (m + 2 < M) ? A[(size_t)(k0 + kl) * lda + m + 2] : 0.f;
                a.w = (m + 3 < M) ? A[(size_t)(k0 + kl) * lda + m + 3] : 0.f;
            }
            *(float4*)&As[kl][ml] = a;
        } else {
            const int ml = tid >> 2;
            const int kl = (tid & 3) * 4;
            const int m  = m0 + ml;
            float4 a = make_float4(0.f, 0.f, 0.f, 0.f);
            if (m < M) a = *(const float4*)&A[(size_t)m * lda + k0 + kl];
            As[kl + 0][ml] = a.x;
            As[kl + 1][ml] = a.y;
            As[kl + 2][ml] = a.z;
            As[kl + 3][ml] = a.w;
        }
        {
            const int kl = tid >> 4;
            const int nl = (tid & 15) * 4;
            *(float4*)&Bs[kl][nl] = *(const float4*)&B[(size_t)(k0 + kl) * Ncol + n0 + nl];
        }
        __syncthreads();
#pragma unroll
        for (int k = 0; k < 16; k++) {
            float4 a = *(float4*)&As[k][ty * 4];
            float4 b = *(float4*)&Bs[k][tx * 4];
            float av[4] = {a.x, a.y, a.z, a.w};
            float bv[4] = {b.x, b.y, b.z, b.w};
#pragma unroll
            for (int i = 0; i < 4; i++)
#pragma unroll
                for (int j = 0; j < 4; j++) acc[i][j] += av[i] * bv[j];
        }
        __syncthreads();
    }
#pragma unroll
    for (int i = 0; i < 4; i++) {
        const int m = m0 + ty * 4 + i;
        if (m < M) {
            float4 v = make_float4(acc[i][0], acc[i][1], acc[i][2], acc[i][3]);
            *(float4*)&C[(size_t)m * Ncol + n0 + tx * 4] = v;
        }
    }
}

// ---------------- per-node attention dots: one warp per (node, head) -------
__global__ void node_dot(const float* __restrict__ h, const float* __restrict__ ws,
                         const float* __restrict__ wd, float* __restrict__ asrc,
                         float* __restrict__ adst, int C, int H)
{
    const int w    = (blockIdx.x * blockDim.x + threadIdx.x) >> 5;
    const int lane = threadIdx.x & 31;
    if (w >= NN * H) return;
    const int n = w / H, hd = w - n * H;
    const float* hp = h + (size_t)n * H * C + hd * C;
    float s1 = 0.f, s2 = 0.f;
    for (int c = lane; c < C; c += 32) {
        const float v = hp[c];
        s1 += v * ws[hd * C + c];
        s2 += v * wd[hd * C + c];
    }
#pragma unroll
    for (int o = 16; o; o >>= 1) {
        s1 += __shfl_down_sync(0xffffffffu, s1, o);
        s2 += __shfl_down_sync(0xffffffffu, s2, o);
    }
    if (lane == 0) { asrc[w] = s1; adst[w] = s2; }
}

// ce[h] = sum_c We[h*C+c] * ae[h*C+c]  (edge attention collapses to scalar/head)
__global__ void ce_kernel(const float* __restrict__ We, const float* __restrict__ ae,
                          float* __restrict__ ce, int C, int H)
{
    const int h = threadIdx.x;
    if (h >= H) return;
    float s = 0.f;
    for (int c = 0; c < C; c++) s += We[h * C + c] * ae[h * C + c];
    ce[h] = s;
}

__global__ void init_stats(float* __restrict__ amax, float* __restrict__ den, int n)
{
    const int i = blockIdx.x * blockDim.x + threadIdx.x;
    if (i < n) { amax[i] = -INFINITY; den[i] = 0.f; }
}

__global__ void zero_fill4(float4* __restrict__ p, int n4)
{
    const int i = blockIdx.x * blockDim.x + threadIdx.x;
    if (i < n4) p[i] = make_float4(0.f, 0.f, 0.f, 0.f);
}

__device__ __forceinline__ void atomicMaxF(float* addr, float v)
{
    if (v >= 0.f) atomicMax((int*)addr, __float_as_int(v));
    else          atomicMin((unsigned int*)addr, __float_as_uint(v));
}

// pass A: leaky logits + segment max over dst
__global__ void edge_logits(const int* __restrict__ src, const int* __restrict__ dst,
                            const float* __restrict__ ew, const float* __restrict__ asrc,
                            const float* __restrict__ adst, const float* __restrict__ ce,
                            float* __restrict__ logit, float* __restrict__ amax, int H)
{
    const int idx = blockIdx.x * blockDim.x + threadIdx.x;
    if (idx >= EE * H) return;
    const int e = idx / H, h = idx - e * H;
    const int s = src[e], d = dst[e];
    float v = asrc[s * H + h] + adst[d * H + h] + ew[e] * ce[h];
    v = (v > 0.f) ? v : 0.2f * v;
    logit[idx] = v;
    atomicMaxF(&amax[d * H + h], v);
}

// pass B: exp(l - max) + segment sum
__global__ void edge_exp(const int* __restrict__ dst, float* __restrict__ exl,
                         const float* __restrict__ amax, float* __restrict__ den, int H)
{
    const int idx = blockIdx.x * blockDim.x + threadIdx.x;
    if (idx >= EE * H) return;
    const int e = idx / H, h = idx - e * H;
    const int d = dst[e];
    const float ex = expf(exl[idx] - amax[d * H + h]);
    exl[idx] = ex;
    atomicAdd(&den[d * H + h], ex);
}

// pass C: out[dst] += alpha * h[src]; one block per edge, 4 channels/thread
__global__ void aggregate(const int* __restrict__ src, const int* __restrict__ dst,
                          const float* __restrict__ hw, const float* __restrict__ exb,
                          const float* __restrict__ den, float* __restrict__ out,
                          int C, int H)
{
    const int e = blockIdx.x;
    const int s = src[e], d = dst[e];
    const int HCl = H * C;
    const int c4 = threadIdx.x * 4;
    if (c4 >= HCl) return;
    const int h = c4 / C;
    const float alpha = exb[(size_t)e * H + h] / (den[d * H + h] + 1e-16f);
    const float4 v = *(const float4*)&hw[(size_t)s * HCl + c4];
    float* o = &out[(size_t)d * HCl + c4];
    atomicAdd(o + 0, v.x * alpha);
    atomicAdd(o + 1, v.y * alpha);
    atomicAdd(o + 2, v.z * alpha);
    atomicAdd(o + 3, v.w * alpha);
}

__global__ void bias_act(const float* __restrict__ in, const float* __restrict__ b,
                         float* __restrict__ out, int total, int cols, int do_relu)
{
    const int i = blockIdx.x * blockDim.x + threadIdx.x;
    if (i >= total) return;
    float v = in[i] + b[i % cols];
    if (do_relu) v = (v > 0.f) ? v : 0.f;
    out[i] = v;
}

// ---------------------------------------------------------------------------
extern "C" void kernel_launch(void* const* d_in, const int* in_sizes, int n_in,
                              void* d_out, int out_size)
{
    (void)in_sizes; (void)n_in; (void)out_size;

    const float* x   = (const float*)d_in[0];
    const int*   ei  = (const int*)  d_in[1];
    const float* ew  = (const float*)d_in[2];
    const float* W1  = (const float*)d_in[3];
    const float* as1 = (const float*)d_in[4];
    const float* ad1 = (const float*)d_in[5];
    const float* We1 = (const float*)d_in[6];
    const float* ae1 = (const float*)d_in[7];
    const float* b1  = (const float*)d_in[8];
    const float* W2  = (const float*)d_in[9];
    const float* as2 = (const float*)d_in[10];
    const float* ad2 = (const float*)d_in[11];
    const float* We2 = (const float*)d_in[12];
    const float* ae2 = (const float*)d_in[13];
    const float* b2  = (const float*)d_in[14];
    const float* W3  = (const float*)d_in[15];
    const float* as3 = (const float*)d_in[16];
    const float* ad3 = (const float*)d_in[17];
    const float* We3 = (const float*)d_in[18];
    const float* ae3 = (const float*)d_in[19];
    const float* b3  = (const float*)d_in[20];
    const int* src = ei;
    const int* dst = ei + EE;
    float* outp = (float*)d_out;

    float *hw, *agg, *hin, *asrc, *adst, *amax, *den, *exb, *ce;
    cudaGetSymbolAddress((void**)&hw,   g_hw);
    cudaGetSymbolAddress((void**)&agg,  g_agg);
    cudaGetSymbolAddress((void**)&hin,  g_hin);
    cudaGetSymbolAddress((void**)&asrc, g_asrc);
    cudaGetSymbolAddress((void**)&adst, g_adst);
    cudaGetSymbolAddress((void**)&amax, g_amax);
    cudaGetSymbolAddress((void**)&den,  g_den);
    cudaGetSymbolAddress((void**)&exb,  g_ex);
    cudaGetSymbolAddress((void**)&ce,   g_ce);

    const int MB = (NN + 63) / 64;

    // ---------------- Layer 1 (in=SEQ via transposed x, out=HC) ------------
    gemm64<true><<<dim3(HC / 64, MB), 256>>>(x, W1, hw, NN, SEQL, HC, NN);
    node_dot<<<(NN * NH * 32 + 255) / 256, 256>>>(hw, as1, ad1, asrc, adst, HIDC, NH);
    ce_kernel<<<1, NH>>>(We1, ae1, ce, HIDC, NH);
    init_stats<<<(NN * NH + 255) / 256, 256>>>(amax, den, NN * NH);
    edge_logits<<<(EE * NH + 255) / 256, 256>>>(src, dst, ew, asrc, adst, ce, exb, amax, NH);
    edge_exp<<<(EE * NH + 255) / 256, 256>>>(dst, exb, amax, den, NH);
    zero_fill4<<<(NN * HC / 4 + 255) / 256, 256>>>((float4*)agg, NN * HC / 4);
    aggregate<<<EE, 256>>>(src, dst, hw, exb, den, agg, HIDC, NH);
    bias_act<<<(NN * HC + 255) / 256, 256>>>(agg, b1, hin, NN * HC, HC, 1);

    // ---------------- Layer 2 (in=HC, out=HC) ------------------------------
    gemm64<false><<<dim3(HC / 64, MB), 256>>>(hin, W2, hw, NN, HC, HC, HC);
    node_dot<<<(NN * NH * 32 + 255) / 256, 256>>>(hw, as2, ad2, asrc, adst, HIDC, NH);
    ce_kernel<<<1, NH>>>(We2, ae2, ce, HIDC, NH);
    init_stats<<<(NN * NH + 255) / 256, 256>>>(amax, den, NN * NH);
    edge_logits<<<(EE * NH + 255) / 256, 256>>>(src, dst, ew, asrc, adst, ce, exb, amax, NH);
    edge_exp<<<(EE * NH + 255) / 256, 256>>>(dst, exb, amax, den, NH);
    zero_fill4<<<(NN * HC / 4 + 255) / 256, 256>>>((float4*)agg, NN * HC / 4);
    aggregate<<<EE, 256>>>(src, dst, hw, exb, den, agg, HIDC, NH);
    bias_act<<<(NN * HC + 255) / 256, 256>>>(agg, b2, hin, NN * HC, HC, 1);

    // ---------------- Layer 3 (in=HC, out=OUT, heads=1, no concat) ---------
    gemm64<false><<<dim3(OUTC / 64, MB), 256>>>(hin, W3, hw, NN, HC, OUTC, HC);
    node_dot<<<(NN * 32 + 255) / 256, 256>>>(hw, as3, ad3, asrc, adst, OUTC, 1);
    ce_kernel<<<1, 1>>>(We3, ae3, ce, OUTC, 1);
    init_stats<<<(NN + 255) / 256, 256>>>(amax, den, NN);
    edge_logits<<<(EE + 255) / 256, 256>>>(src, dst, ew, asrc, adst, ce, exb, amax, 1);
    edge_exp<<<(EE + 255) / 256, 256>>>(dst, exb, amax, den, 1);
    zero_fill4<<<(NN * OUTC / 4 + 255) / 256, 256>>>((float4*)agg, NN * OUTC / 4);
    aggregate<<<EE, 192>>>(src, dst, hw, exb, den, agg, OUTC, 1);
    bias_act<<<(NN * OUTC + 255) / 256, 256>>>(agg, b3, outp, NN * OUTC, OUTC, 0);
}

// round 4
// speedup vs baseline: 1.6607x; 1.6607x over previous
#include <cuda_runtime.h>
#include <math.h>
#include <stdint.h>

#define NN   10000
#define EE   160000
#define SEQL 96
#define HIDC 128
#define NH   8
#define HC   1024   // NH*HIDC
#define OUTC 768

// ---------------- scratch (device globals; no allocation allowed) ----------
__device__ float g_hw [NN * HC];   // W-transformed features (message source)
__device__ float g_hin[NN * HC];   // layer input (after relu+bias)
__device__ float g_asrc[NN * NH];
__device__ float g_adst[NN * NH];
__device__ float g_amax[NN * NH];
__device__ float g_den [NN * NH];
__device__ float g_ex  [EE * NH];  // logits, then exp values
__device__ float g_ce  [NH];
__device__ int   g_deg [NN];
__device__ int   g_rowptr[NN + 1];
__device__ int   g_cursor[NN];
__device__ int   g_csr[EE];

// ======================= TF32 tensor-core GEMM =============================
// C[M,Ncol] = A @ B, fp32 in/out, 3xTF32 decomposition (fp32-level accuracy).
// CTA tile 128x128, 16 warps (512 thr), warp tile 32x32, K-chunk 16, dbl-buf.
// TA=false: A row-major [M,K] (lda=K). TA=true: A is [K,M] (lda=M stride).

__device__ __forceinline__ uint32_t f2tf(float x) {
    uint32_t r;
    asm("cvt.rna.tf32.f32 %0, %1;" : "=r"(r) : "f"(x));
    return r;
}

__device__ __forceinline__ void mma_tf32(float* c, const uint32_t* a, const uint32_t* b) {
    asm volatile(
        "mma.sync.aligned.m16n8k8.row.col.f32.tf32.tf32.f32 "
        "{%0,%1,%2,%3},{%4,%5,%6,%7},{%8,%9},{%0,%1,%2,%3};\n"
        : "+f"(c[0]), "+f"(c[1]), "+f"(c[2]), "+f"(c[3])
        : "r"(a[0]), "r"(a[1]), "r"(a[2]), "r"(a[3]), "r"(b[0]), "r"(b[1]));
}

template <bool TA>
__global__ __launch_bounds__(512) void gemm_tc(
    const float* __restrict__ A, const float* __restrict__ B,
    float* __restrict__ C, int M, int K, int Ncol, int lda)
{
    __shared__ __align__(16) float As[2][128][20];
    __shared__ __align__(16) float Bs[2][128][20];

    const int tid  = threadIdx.x;
    const int lane = tid & 31;
    const int w    = tid >> 5;
    const int wr   = w >> 2, wc = w & 3;     // 4x4 warp grid
    const int m0   = blockIdx.y * 128, n0 = blockIdx.x * 128;
    const int r    = lane >> 2, q = lane & 3;

    float acc[2][4][4];
#pragma unroll
    for (int t = 0; t < 2; t++)
#pragma unroll
        for (int j = 0; j < 4; j++)
#pragma unroll
            for (int i = 0; i < 4; i++) acc[t][j][i] = 0.f;

    // load-index precompute
    const int mA_rm = tid >> 2, kA_rm = (tid & 3) * 4;   // row-major A
    const int kA_t  = tid >> 5, mA_t  = (tid & 31) * 4;  // transposed A
    const int kB    = tid >> 5, nB    = (tid & 31) * 4;

    const int nchunks = K / 16;
    int buf = 0;

    // ---- LDG of chunk -> registers ----
    auto ldgA = [&](int k0, float4& av) {
        if (!TA) {
            const int m = m0 + mA_rm;
            av = (m < M) ? *(const float4*)&A[(size_t)m * lda + k0 + kA_rm]
                         : make_float4(0.f, 0.f, 0.f, 0.f);
        } else {
            const int m = m0 + mA_t;
            const size_t base = (size_t)(k0 + kA_t) * lda;
            if (m + 3 < M) av = *(const float4*)&A[base + m];
            else {
                av.x = (m + 0 < M) ? A[base + m + 0] : 0.f;
                av.y = (m + 1 < M) ? A[base + m + 1] : 0.f;
                av.z = (m + 2 < M) ? A[base + m + 2] : 0.f;
                av.w = (m + 3 < M) ? A[base + m + 3] : 0.f;
            }
        }
    };
    auto ldgB = [&](int k0, float4& bv) {
        bv = *(const float4*)&B[(size_t)(k0 + kB) * Ncol + n0 + nB];
    };
    auto stsAB = [&](int b, const float4& av, const float4& bv) {
        if (!TA) {
            *(float4*)&As[b][mA_rm][kA_rm] = av;
        } else {
            As[b][mA_t + 0][kA_t] = av.x;
            As[b][mA_t + 1][kA_t] = av.y;
            As[b][mA_t + 2][kA_t] = av.z;
            As[b][mA_t + 3][kA_t] = av.w;
        }
        Bs[b][nB + 0][kB] = bv.x;
        Bs[b][nB + 1][kB] = bv.y;
        Bs[b][nB + 2][kB] = bv.z;
        Bs[b][nB + 3][kB] = bv.w;
    };

    {
        float4 av, bv;
        ldgA(0, av); ldgB(0, bv);
        stsAB(0, av, bv);
    }
    __syncthreads();

    for (int c = 0; c < nchunks; c++) {
        float4 av, bv;
        const bool has = (c + 1 < nchunks);
        if (has) { ldgA((c + 1) * 16, av); ldgB((c + 1) * 16, bv); }

#pragma unroll
        for (int ks = 0; ks < 2; ks++) {
            const int kb = ks * 8;
            uint32_t ahi[2][4], alo[2][4], bhi[4][2], blo[4][2];
#pragma unroll
            for (int t = 0; t < 2; t++) {
                const int row = wr * 32 + t * 16 + r;
                const float a0 = As[buf][row][kb + q];
                const float a1 = As[buf][row + 8][kb + q];
                const float a2 = As[buf][row][kb + q + 4];
                const float a3 = As[buf][row + 8][kb + q + 4];
                ahi[t][0] = f2tf(a0); alo[t][0] = f2tf(a0 - __uint_as_float(ahi[t][0]));
                ahi[t][1] = f2tf(a1); alo[t][1] = f2tf(a1 - __uint_as_float(ahi[t][1]));
                ahi[t][2] = f2tf(a2); alo[t][2] = f2tf(a2 - __uint_as_float(ahi[t][2]));
                ahi[t][3] = f2tf(a3); alo[t][3] = f2tf(a3 - __uint_as_float(ahi[t][3]));
            }
#pragma unroll
            for (int j = 0; j < 4; j++) {
                const int nrow = wc * 32 + j * 8 + r;
                const float b0 = Bs[buf][nrow][kb + q];
                const float b1 = Bs[buf][nrow][kb + 4 + q];
                bhi[j][0] = f2tf(b0); blo[j][0] = f2tf(b0 - __uint_as_float(bhi[j][0]));
                bhi[j][1] = f2tf(b1); blo[j][1] = f2tf(b1 - __uint_as_float(bhi[j][1]));
            }
#pragma unroll
            for (int t = 0; t < 2; t++)
#pragma unroll
                for (int j = 0; j < 4; j++) {
                    mma_tf32(acc[t][j], alo[t], bhi[j]);
                    mma_tf32(acc[t][j], ahi[t], blo[j]);
                    mma_tf32(acc[t][j], ahi[t], bhi[j]);
                }
        }

        if (has) stsAB(buf ^ 1, av, bv);
        __syncthreads();
        buf ^= 1;
    }

    // epilogue
#pragma unroll
    for (int t = 0; t < 2; t++) {
        const int r0 = m0 + wr * 32 + t * 16 + r;
        const int r1 = r0 + 8;
#pragma unroll
        for (int j = 0; j < 4; j++) {
            const int cb = n0 + wc * 32 + j * 8 + 2 * q;
            if (r0 < M) *(float2*)&C[(size_t)r0 * Ncol + cb] = make_float2(acc[t][j][0], acc[t][j][1]);
            if (r1 < M) *(float2*)&C[(size_t)r1 * Ncol + cb] = make_float2(acc[t][j][2], acc[t][j][3]);
        }
    }
}

// ---------------- per-node attention dots: one warp per (node, head) -------
__global__ void node_dot(const float* __restrict__ h, const float* __restrict__ ws,
                         const float* __restrict__ wd, float* __restrict__ asrc,
                         float* __restrict__ adst, int C, int H)
{
    const int w    = (blockIdx.x * blockDim.x + threadIdx.x) >> 5;
    const int lane = threadIdx.x & 31;
    if (w >= NN * H) return;
    const int n = w / H, hd = w - n * H;
    const float* hp = h + (size_t)n * H * C + hd * C;
    float s1 = 0.f, s2 = 0.f;
    for (int c = lane; c < C; c += 32) {
        const float v = hp[c];
        s1 += v * ws[hd * C + c];
        s2 += v * wd[hd * C + c];
    }
#pragma unroll
    for (int o = 16; o; o >>= 1) {
        s1 += __shfl_down_sync(0xffffffffu, s1, o);
        s2 += __shfl_down_sync(0xffffffffu, s2, o);
    }
    if (lane == 0) { asrc[w] = s1; adst[w] = s2; }
}

__global__ void ce_kernel(const float* __restrict__ We, const float* __restrict__ ae,
                          float* __restrict__ ce, int C, int H)
{
    const int h = threadIdx.x;
    if (h >= H) return;
    float s = 0.f;
    for (int c = 0; c < C; c++) s += We[h * C + c] * ae[h * C + c];
    ce[h] = s;
}

__global__ void init_stats(float* __restrict__ amax, float* __restrict__ den, int n)
{
    const int i = blockIdx.x * blockDim.x + threadIdx.x;
    if (i < n) { amax[i] = -INFINITY; den[i] = 0.f; }
}

__device__ __forceinline__ void atomicMaxF(float* addr, float v)
{
    if (v >= 0.f) atomicMax((int*)addr, __float_as_int(v));
    else          atomicMin((unsigned int*)addr, __float_as_uint(v));
}

__global__ void edge_logits(const int* __restrict__ src, const int* __restrict__ dst,
                            const float* __restrict__ ew, const float* __restrict__ asrc,
                            const float* __restrict__ adst, const float* __restrict__ ce,
                            float* __restrict__ logit, float* __restrict__ amax, int H)
{
    const int idx = blockIdx.x * blockDim.x + threadIdx.x;
    if (idx >= EE * H) return;
    const int e = idx / H, h = idx - e * H;
    const int s = src[e], d = dst[e];
    float v = asrc[s * H + h] + adst[d * H + h] + ew[e] * ce[h];
    v = (v > 0.f) ? v : 0.2f * v;
    logit[idx] = v;
    atomicMaxF(&amax[d * H + h], v);
}

__global__ void edge_exp(const int* __restrict__ dst, float* __restrict__ exl,
                         const float* __restrict__ amax, float* __restrict__ den, int H)
{
    const int idx = blockIdx.x * blockDim.x + threadIdx.x;
    if (idx >= EE * H) return;
    const int e = idx / H, h = idx - e * H;
    const int d = dst[e];
    const float ex = expf(exl[idx] - amax[d * H + h]);
    exl[idx] = ex;
    atomicAdd(&den[d * H + h], ex);
}

// ======================= CSR build (once per launch) =======================
__global__ void zero_deg(int* __restrict__ deg)
{
    const int i = blockIdx.x * blockDim.x + threadIdx.x;
    if (i < NN) deg[i] = 0;
}

__global__ void count_deg(const int* __restrict__ dst, int* __restrict__ deg)
{
    const int e = blockIdx.x * blockDim.x + threadIdx.x;
    if (e < EE) atomicAdd(&deg[dst[e]], 1);
}

__global__ void scan_rowptr(const int* __restrict__ deg, int* __restrict__ rowptr)
{
    __shared__ int ssum[1024];
    const int t = threadIdx.x;
    const int CHK = (NN + 1023) / 1024;
    const int base = t * CHK;
    int s = 0;
    for (int i = 0; i < CHK; i++) {
        const int idx = base + i;
        if (idx < NN) s += deg[idx];
    }
    ssum[t] = s;
    __syncthreads();
    for (int off = 1; off < 1024; off <<= 1) {
        int v = (t >= off) ? ssum[t - off] : 0;
        __syncthreads();
        ssum[t] += v;
        __syncthreads();
    }
    int run = ssum[t] - s;   // exclusive prefix of this chunk
    for (int i = 0; i < CHK; i++) {
        const int idx = base + i;
        if (idx < NN) { rowptr[idx] = run; run += deg[idx]; }
    }
    if (t == 0) rowptr[NN] = EE;
}

__global__ void init_cursor(const int* __restrict__ rowptr, int* __restrict__ cursor)
{
    const int i = blockIdx.x * blockDim.x + threadIdx.x;
    if (i < NN) cursor[i] = rowptr[i];
}

__global__ void scatter_csr(const int* __restrict__ dst, int* __restrict__ cursor,
                            int* __restrict__ csr)
{
    const int e = blockIdx.x * blockDim.x + threadIdx.x;
    if (e >= EE) return;
    const int pos = atomicAdd(&cursor[dst[e]], 1);
    csr[pos] = e;
}

// =============== CSR aggregation: one block per node, fused bias+act =======
template <int CPH, int H, bool RELU>
__global__ __launch_bounds__(256) void agg_csr(
                        const int* __restrict__ rowptr, const int* __restrict__ csr,
                        const int* __restrict__ src, const float* __restrict__ hw,
                        const float* __restrict__ exb, const float* __restrict__ den,
                        const float* __restrict__ bias, float* __restrict__ out)
{
    constexpr int TOT = CPH * H;
    constexpr int NT  = TOT / 4;
    const int d   = blockIdx.x;
    const int tid = threadIdx.x;
    const int c4  = tid * 4;
    const int h   = c4 / CPH;

    __shared__ float sinv[H];
    __shared__ int   ssrc[64];
    __shared__ int   sei [64];
    __shared__ float sal [64 * H];

    if (tid < H) sinv[tid] = 1.f / (den[d * H + tid] + 1e-16f);

    float4 acc = make_float4(0.f, 0.f, 0.f, 0.f);
    const int b0 = rowptr[d], b1 = rowptr[d + 1];

    for (int base = b0; base < b1; base += 64) {
        const int cnt = min(64, b1 - base);
        __syncthreads();
        if (tid < cnt) {
            const int e = csr[base + tid];
            sei[tid]  = e;
            ssrc[tid] = src[e];
        }
        __syncthreads();
        for (int idx = tid; idx < cnt * H; idx += NT) {
            const int i = idx / H, hh = idx - i * H;
            sal[idx] = exb[(size_t)sei[i] * H + hh] * sinv[hh];
        }
        __syncthreads();
#pragma unroll 4
        for (int i = 0; i < cnt; i++) {
            const float4 v = *(const float4*)&hw[(size_t)ssrc[i] * TOT + c4];
            const float  al = sal[i * H + h];
            acc.x += v.x * al;
            acc.y += v.y * al;
            acc.z += v.z * al;
            acc.w += v.w * al;
        }
    }

    const float4 bb = *(const float4*)&bias[c4];
    acc.x += bb.x; acc.y += bb.y; acc.z += bb.z; acc.w += bb.w;
    if (RELU) {
        acc.x = fmaxf(acc.x, 0.f);
        acc.y = fmaxf(acc.y, 0.f);
        acc.z = fmaxf(acc.z, 0.f);
        acc.w = fmaxf(acc.w, 0.f);
    }
    *(float4*)&out[(size_t)d * TOT + c4] = acc;
}

// ---------------------------------------------------------------------------
extern "C" void kernel_launch(void* const* d_in, const int* in_sizes, int n_in,
                              void* d_out, int out_size)
{
    (void)in_sizes; (void)n_in; (void)out_size;

    const float* x   = (const float*)d_in[0];
    const int*   ei  = (const int*)  d_in[1];
    const float* ew  = (const float*)d_in[2];
    const float* W1  = (const float*)d_in[3];
    const float* as1 = (const float*)d_in[4];
    const float* ad1 = (const float*)d_in[5];
    const float* We1 = (const float*)d_in[6];
    const float* ae1 = (const float*)d_in[7];
    const float* b1  = (const float*)d_in[8];
    const float* W2  = (const float*)d_in[9];
    const float* as2 = (const float*)d_in[10];
    const float* ad2 = (const float*)d_in[11];
    const float* We2 = (const float*)d_in[12];
    const float* ae2 = (const float*)d_in[13];
    const float* b2  = (const float*)d_in[14];
    const float* W3  = (const float*)d_in[15];
    const float* as3 = (const float*)d_in[16];
    const float* ad3 = (const float*)d_in[17];
    const float* We3 = (const float*)d_in[18];
    const float* ae3 = (const float*)d_in[19];
    const float* b3  = (const float*)d_in[20];
    const int* src = ei;
    const int* dst = ei + EE;
    float* outp = (float*)d_out;

    float *hw, *hin, *asrc, *adst, *amax, *den, *exb, *ce;
    int *deg, *rowptr, *cursor, *csr;
    cudaGetSymbolAddress((void**)&hw,     g_hw);
    cudaGetSymbolAddress((void**)&hin,    g_hin);
    cudaGetSymbolAddress((void**)&asrc,   g_asrc);
    cudaGetSymbolAddress((void**)&adst,   g_adst);
    cudaGetSymbolAddress((void**)&amax,   g_amax);
    cudaGetSymbolAddress((void**)&den,    g_den);
    cudaGetSymbolAddress((void**)&exb,    g_ex);
    cudaGetSymbolAddress((void**)&ce,     g_ce);
    cudaGetSymbolAddress((void**)&deg,    g_deg);
    cudaGetSymbolAddress((void**)&rowptr, g_rowptr);
    cudaGetSymbolAddress((void**)&cursor, g_cursor);
    cudaGetSymbolAddress((void**)&csr,    g_csr);

    const int MB = (NN + 127) / 128;

    // ---- CSR build (dst-indexed, reused by all layers) ----
    zero_deg<<<(NN + 255) / 256, 256>>>(deg);
    count_deg<<<(EE + 255) / 256, 256>>>(dst, deg);
    scan_rowptr<<<1, 1024>>>(deg, rowptr);
    init_cursor<<<(NN + 255) / 256, 256>>>(rowptr, cursor);
    scatter_csr<<<(EE + 255) / 256, 256>>>(dst, cursor, csr);

    // ---------------- Layer 1 (in=SEQ via transposed x, out=HC) ------------
    gemm_tc<true><<<dim3(HC / 128, MB), 512>>>(x, W1, hw, NN, SEQL, HC, NN);
    node_dot<<<(NN * NH * 32 + 255) / 256, 256>>>(hw, as1, ad1, asrc, adst, HIDC, NH);
    ce_kernel<<<1, NH>>>(We1, ae1, ce, HIDC, NH);
    init_stats<<<(NN * NH + 255) / 256, 256>>>(amax, den, NN * NH);
    edge_logits<<<(EE * NH + 255) / 256, 256>>>(src, dst, ew, asrc, adst, ce, exb, amax, NH);
    edge_exp<<<(EE * NH + 255) / 256, 256>>>(dst, exb, amax, den, NH);
    agg_csr<HIDC, NH, true><<<NN, HC / 4>>>(rowptr, csr, src, hw, exb, den, b1, hin);

    // ---------------- Layer 2 (in=HC, out=HC) ------------------------------
    gemm_tc<false><<<dim3(HC / 128, MB), 512>>>(hin, W2, hw, NN, HC, HC, HC);
    node_dot<<<(NN * NH * 32 + 255) / 256, 256>>>(hw, as2, ad2, asrc, adst, HIDC, NH);
    ce_kernel<<<1, NH>>>(We2, ae2, ce, HIDC, NH);
    init_stats<<<(NN * NH + 255) / 256, 256>>>(amax, den, NN * NH);
    edge_logits<<<(EE * NH + 255) / 256, 256>>>(src, dst, ew, asrc, adst, ce, exb, amax, NH);
    edge_exp<<<(EE * NH + 255) / 256, 256>>>(dst, exb, amax, den, NH);
    agg_csr<HIDC, NH, true><<<NN, HC / 4>>>(rowptr, csr, src, hw, exb, den, b2, hin);

    // ---------------- Layer 3 (in=HC, out=OUT, heads=1, no concat) ---------
    gemm_tc<false><<<dim3(OUTC / 128, MB), 512>>>(hin, W3, hw, NN, HC, OUTC, HC);
    node_dot<<<(NN * 32 + 255) / 256, 256>>>(hw, as3, ad3, asrc, adst, OUTC, 1);
    ce_kernel<<<1, 1>>>(We3, ae3, ce, OUTC, 1);
    init_stats<<<(NN + 255) / 256, 256>>>(amax, den, NN);
    edge_logits<<<(EE + 255) / 256, 256>>>(src, dst, ew, asrc, adst, ce, exb, amax, 1);
    edge_exp<<<(EE + 255) / 256, 256>>>(dst, exb, amax, den, 1);
    agg_csr<OUTC, 1, false><<<NN, OUTC / 4>>>(rowptr, csr, src, hw, exb, den, b3, outp);
}

// round 5
// speedup vs baseline: 3.2658x; 1.9665x over previous
#include <cuda_runtime.h>
#include <cuda_bf16.h>
#include <math.h>
#include <stdint.h>

#define NN   10000
#define EE   160000
#define SEQL 96
#define HIDC 128
#define NH   8
#define HC   1024   // NH*HIDC
#define OUTC 768

// ---------------- scratch (device globals; no allocation allowed) ----------
__device__ float g_hw [NN * HC];   // W-transformed features (message source)
__device__ float g_hin[NN * HC];   // layer input (after relu+bias)
__device__ float g_asrc[NN * NH];
__device__ float g_adst[NN * NH];
__device__ float g_amax[NN * NH];
__device__ float g_den [NN * NH];
__device__ float g_ex  [EE * NH];  // logits, then exp values
__device__ float g_ce  [NH];
__device__ int   g_deg [NN];
__device__ int   g_rowptr[NN + 1];
__device__ int   g_cursor[NN];
__device__ int   g_csr[EE];

// ======================= bf16x3 tensor-core GEMM ===========================
// C[M,Ncol] = A @ B, fp32 in/out. Each fp32 split at STS time into bf16
// hi + lo; accumulate ahi*bhi + ahi*blo + alo*bhi (drop lo*lo ~ 2^-16 rel).
// CTA tile 128x128, 256 thr (8 warps, 2x4 grid), warp tile 64x32.
// K-chunk 32 (two m16n8k16 K-passes). Fragments via ldmatrix.x4.
// TA=false: A row-major [M,K] (lda=K). TA=true: A is [K,M] (lda = M stride).

#define SMSA 40    // A smem row stride in bf16 (80B; 5m mod 8 distinct -> ldmatrix conflict-free)
#define SMSB 136   // B smem row stride in bf16 (272B; 17k mod 8 distinct)

__device__ __forceinline__ uint32_t sm32(const void* p) {
    return (uint32_t)__cvta_generic_to_shared(p);
}

__device__ __forceinline__ void ldm_x4(uint32_t* d, uint32_t addr) {
    asm volatile("ldmatrix.sync.aligned.m8n8.x4.shared.b16 {%0,%1,%2,%3}, [%4];"
                 : "=r"(d[0]), "=r"(d[1]), "=r"(d[2]), "=r"(d[3]) : "r"(addr));
}

__device__ __forceinline__ void ldm_x4_t(uint32_t* d, uint32_t addr) {
    asm volatile("ldmatrix.sync.aligned.m8n8.x4.trans.shared.b16 {%0,%1,%2,%3}, [%4];"
                 : "=r"(d[0]), "=r"(d[1]), "=r"(d[2]), "=r"(d[3]) : "r"(addr));
}

__device__ __forceinline__ void mma_bf16(float* c, const uint32_t* a, const uint32_t* b) {
    asm volatile(
        "mma.sync.aligned.m16n8k16.row.col.f32.bf16.bf16.f32 "
        "{%0,%1,%2,%3},{%4,%5,%6,%7},{%8,%9},{%0,%1,%2,%3};"
        : "+f"(c[0]), "+f"(c[1]), "+f"(c[2]), "+f"(c[3])
        : "r"(a[0]), "r"(a[1]), "r"(a[2]), "r"(a[3]), "r"(b[0]), "r"(b[1]));
}

// split two floats into packed hi/lo bf16x2
__device__ __forceinline__ void split2(float x0, float x1,
                                       __nv_bfloat162& hi, __nv_bfloat162& lo) {
    hi = __float22bfloat162_rn(make_float2(x0, x1));
    lo = __float22bfloat162_rn(make_float2(x0 - __low2float(hi),
                                           x1 - __high2float(hi)));
}

template <bool TA>
__global__ __launch_bounds__(256) void gemm_bf3(
    const float* __restrict__ A, const float* __restrict__ B,
    float* __restrict__ C, int M, int K, int Ncol, int lda)
{
    __shared__ __align__(16) __nv_bfloat16 Ah[128][SMSA];
    __shared__ __align__(16) __nv_bfloat16 Al[128][SMSA];
    __shared__ __align__(16) __nv_bfloat16 Bh[32][SMSB];
    __shared__ __align__(16) __nv_bfloat16 Bl[32][SMSB];

    const int tid  = threadIdx.x;
    const int lane = tid & 31;
    const int w    = tid >> 5;
    const int wr   = w >> 2, wc = w & 3;      // 2x4 warp grid
    const int m0   = blockIdx.y * 128, n0 = blockIdx.x * 128;
    const int r    = lane >> 2, q = lane & 3;

    float acc[4][4][4];                        // [m-tile][n-tile][4]
#pragma unroll
    for (int a = 0; a < 4; a++)
#pragma unroll
        for (int b = 0; b < 4; b++)
#pragma unroll
            for (int i = 0; i < 4; i++) acc[a][b][i] = 0.f;

    float4 av[4], bv[4];

    auto ldg = [&](int k0) {
        if (!TA) {
#pragma unroll
            for (int i = 0; i < 4; i++) {
                const int idx = i * 256 + tid;
                const int m = idx >> 3, kq = (idx & 7) * 4;
                const int gm = m0 + m;
                av[i] = (gm < M) ? *(const float4*)&A[(size_t)gm * lda + k0 + kq]
                                 : make_float4(0.f, 0.f, 0.f, 0.f);
            }
        } else {
#pragma unroll
            for (int i = 0; i < 4; i++) {
                const int idx = i * 256 + tid;
                const int k = idx >> 5, mq = (idx & 31) * 4;
                const int gm = m0 + mq;
                const float* p = &A[(size_t)(k0 + k) * lda + gm];
                if (gm + 3 < M) av[i] = *(const float4*)p;
                else {
                    av[i].x = (gm + 0 < M) ? p[0] : 0.f;
                    av[i].y = (gm + 1 < M) ? p[1] : 0.f;
                    av[i].z = (gm + 2 < M) ? p[2] : 0.f;
                    av[i].w = (gm + 3 < M) ? p[3] : 0.f;
                }
            }
        }
#pragma unroll
        for (int i = 0; i < 4; i++) {
            const int idx = i * 256 + tid;
            const int k = idx >> 5, nq = (idx & 31) * 4;
            bv[i] = *(const float4*)&B[(size_t)(k0 + k) * Ncol + n0 + nq];
        }
    };

    auto sts = [&]() {
#pragma unroll
        for (int i = 0; i < 4; i++) {
            const int idx = i * 256 + tid;
            if (!TA) {
                const int m = idx >> 3, kq = (idx & 7) * 4;
                __nv_bfloat162 h01, l01, h23, l23;
                split2(av[i].x, av[i].y, h01, l01);
                split2(av[i].z, av[i].w, h23, l23);
                *(__nv_bfloat162*)&Ah[m][kq]     = h01;
                *(__nv_bfloat162*)&Ah[m][kq + 2] = h23;
                *(__nv_bfloat162*)&Al[m][kq]     = l01;
                *(__nv_bfloat162*)&Al[m][kq + 2] = l23;
            } else {
                const int k = idx >> 5, mq = (idx & 31) * 4;
                const float vv[4] = {av[i].x, av[i].y, av[i].z, av[i].w};
#pragma unroll
                for (int j = 0; j < 4; j++) {
                    const __nv_bfloat16 hi = __float2bfloat16(vv[j]);
                    Ah[mq + j][k] = hi;
                    Al[mq + j][k] = __float2bfloat16(vv[j] - __bfloat162float(hi));
                }
            }
            {
                const int k = idx >> 5, nq = (idx & 31) * 4;
                __nv_bfloat162 h01, l01, h23, l23;
                split2(bv[i].x, bv[i].y, h01, l01);
                split2(bv[i].z, bv[i].w, h23, l23);
                *(__nv_bfloat162*)&Bh[k][nq]     = h01;
                *(__nv_bfloat162*)&Bh[k][nq + 2] = h23;
                *(__nv_bfloat162*)&Bl[k][nq]     = l01;
                *(__nv_bfloat162*)&Bl[k][nq + 2] = l23;
            }
        }
    };

    // one K=16 MMA pass over the resident chunk
    auto pass = [&](int kb) {
        // A fragments: row = m-base + (lane&15), col = kb + 8*(lane>>4)
        const int ar = (lane & 15), ac = kb + 8 * (lane >> 4);
        uint32_t ah[4][4], al[4][4];
#pragma unroll
        for (int mt = 0; mt < 4; mt++) {
            const int row = wr * 64 + mt * 16 + ar;
            ldm_x4(ah[mt], sm32(&Ah[row][ac]));
            ldm_x4(al[mt], sm32(&Al[row][ac]));
        }
        // B fragments (trans): row = kb + (lane&15), col = n-base + 8*(lane>>4)
        const int br = kb + (lane & 15);
        uint32_t bh[2][4], bl[2][4];
#pragma unroll
        for (int g = 0; g < 2; g++) {
            const int col = wc * 32 + g * 16 + 8 * (lane >> 4);
            ldm_x4_t(bh[g], sm32(&Bh[br][col]));
            ldm_x4_t(bl[g], sm32(&Bl[br][col]));
        }
#pragma unroll
        for (int mt = 0; mt < 4; mt++)
#pragma unroll
            for (int nt = 0; nt < 4; nt++) {
                const uint32_t* bH = &bh[nt >> 1][(nt & 1) * 2];
                const uint32_t* bL = &bl[nt >> 1][(nt & 1) * 2];
                mma_bf16(acc[mt][nt], ah[mt], bH);
                mma_bf16(acc[mt][nt], ah[mt], bL);
                mma_bf16(acc[mt][nt], al[mt], bH);
            }
    };

    ldg(0);
    const int nchunks = K / 32;
    for (int c = 0; c < nchunks; c++) {
        sts();
        __syncthreads();
        if (c + 1 < nchunks) ldg((c + 1) * 32);
        pass(0);
        pass(16);
        __syncthreads();
    }

    // epilogue
#pragma unroll
    for (int mt = 0; mt < 4; mt++) {
        const int r0 = m0 + wr * 64 + mt * 16 + r;
        const int r1 = r0 + 8;
#pragma unroll
        for (int nt = 0; nt < 4; nt++) {
            const int col = n0 + wc * 32 + nt * 8 + 2 * q;
            if (r0 < M)
                *(float2*)&C[(size_t)r0 * Ncol + col] = make_float2(acc[mt][nt][0], acc[mt][nt][1]);
            if (r1 < M)
                *(float2*)&C[(size_t)r1 * Ncol + col] = make_float2(acc[mt][nt][2], acc[mt][nt][3]);
        }
    }
}

// ---------------- per-node attention dots: one warp per (node, head) -------
__global__ void node_dot(const float* __restrict__ h, const float* __restrict__ ws,
                         const float* __restrict__ wd, float* __restrict__ asrc,
                         float* __restrict__ adst, int C, int H)
{
    const int w    = (blockIdx.x * blockDim.x + threadIdx.x) >> 5;
    const int lane = threadIdx.x & 31;
    if (w >= NN * H) return;
    const int n = w / H, hd = w - n * H;
    const float* hp = h + (size_t)n * H * C + hd * C;
    float s1 = 0.f, s2 = 0.f;
    for (int c = lane; c < C; c += 32) {
        const float v = hp[c];
        s1 += v * ws[hd * C + c];
        s2 += v * wd[hd * C + c];
    }
#pragma unroll
    for (int o = 16; o; o >>= 1) {
        s1 += __shfl_down_sync(0xffffffffu, s1, o);
        s2 += __shfl_down_sync(0xffffffffu, s2, o);
    }
    if (lane == 0) { asrc[w] = s1; adst[w] = s2; }
}

__global__ void ce_kernel(const float* __restrict__ We, const float* __restrict__ ae,
                          float* __restrict__ ce, int C, int H)
{
    const int h = threadIdx.x;
    if (h >= H) return;
    float s = 0.f;
    for (int c = 0; c < C; c++) s += We[h * C + c] * ae[h * C + c];
    ce[h] = s;
}

__global__ void init_stats(float* __restrict__ amax, float* __restrict__ den, int n)
{
    const int i = blockIdx.x * blockDim.x + threadIdx.x;
    if (i < n) { amax[i] = -INFINITY; den[i] = 0.f; }
}

__device__ __forceinline__ void atomicMaxF(float* addr, float v)
{
    if (v >= 0.f) atomicMax((int*)addr, __float_as_int(v));
    else          atomicMin((unsigned int*)addr, __float_as_uint(v));
}

__global__ void edge_logits(const int* __restrict__ src, const int* __restrict__ dst,
                            const float* __restrict__ ew, const float* __restrict__ asrc,
                            const float* __restrict__ adst, const float* __restrict__ ce,
                            float* __restrict__ logit, float* __restrict__ amax, int H)
{
    const int idx = blockIdx.x * blockDim.x + threadIdx.x;
    if (idx >= EE * H) return;
    const int e = idx / H, h = idx - e * H;
    const int s = src[e], d = dst[e];
    float v = asrc[s * H + h] + adst[d * H + h] + ew[e] * ce[h];
    v = (v > 0.f) ? v : 0.2f * v;
    logit[idx] = v;
    atomicMaxF(&amax[d * H + h], v);
}

__global__ void edge_exp(const int* __restrict__ dst, float* __restrict__ exl,
                         const float* __restrict__ amax, float* __restrict__ den, int H)
{
    const int idx = blockIdx.x * blockDim.x + threadIdx.x;
    if (idx >= EE * H) return;
    const int e = idx / H, h = idx - e * H;
    const int d = dst[e];
    const float ex = expf(exl[idx] - amax[d * H + h]);
    exl[idx] = ex;
    atomicAdd(&den[d * H + h], ex);
}

// ======================= CSR build (once per launch) =======================
__global__ void zero_deg(int* __restrict__ deg)
{
    const int i = blockIdx.x * blockDim.x + threadIdx.x;
    if (i < NN) deg[i] = 0;
}

__global__ void count_deg(const int* __restrict__ dst, int* __restrict__ deg)
{
    const int e = blockIdx.x * blockDim.x + threadIdx.x;
    if (e < EE) atomicAdd(&deg[dst[e]], 1);
}

__global__ void scan_rowptr(const int* __restrict__ deg, int* __restrict__ rowptr)
{
    __shared__ int ssum[1024];
    const int t = threadIdx.x;
    const int CHK = (NN + 1023) / 1024;
    const int base = t * CHK;
    int s = 0;
    for (int i = 0; i < CHK; i++) {
        const int idx = base + i;
        if (idx < NN) s += deg[idx];
    }
    ssum[t] = s;
    __syncthreads();
    for (int off = 1; off < 1024; off <<= 1) {
        int v = (t >= off) ? ssum[t - off] : 0;
        __syncthreads();
        ssum[t] += v;
        __syncthreads();
    }
    int run = ssum[t] - s;   // exclusive prefix of this chunk
    for (int i = 0; i < CHK; i++) {
        const int idx = base + i;
        if (idx < NN) { rowptr[idx] = run; run += deg[idx]; }
    }
    if (t == 0) rowptr[NN] = EE;
}

__global__ void init_cursor(const int* __restrict__ rowptr, int* __restrict__ cursor)
{
    const int i = blockIdx.x * blockDim.x + threadIdx.x;
    if (i < NN) cursor[i] = rowptr[i];
}

__global__ void scatter_csr(const int* __restrict__ dst, int* __restrict__ cursor,
                            int* __restrict__ csr)
{
    const int e = blockIdx.x * blockDim.x + threadIdx.x;
    if (e >= EE) return;
    const int pos = atomicAdd(&cursor[dst[e]], 1);
    csr[pos] = e;
}

// =============== CSR aggregation: one block per node, fused bias+act =======
template <int CPH, int H, bool RELU>
__global__ __launch_bounds__(256) void agg_csr(
                        const int* __restrict__ rowptr, const int* __restrict__ csr,
                        const int* __restrict__ src, const float* __restrict__ hw,
                        const float* __restrict__ exb, const float* __restrict__ den,
                        const float* __restrict__ bias, float* __restrict__ out)
{
    constexpr int TOT = CPH * H;
    constexpr int NT  = TOT / 4;
    const int d   = blockIdx.x;
    const int tid = threadIdx.x;
    const int c4  = tid * 4;
    const int h   = c4 / CPH;

    __shared__ float sinv[H];
    __shared__ int   ssrc[64];
    __shared__ int   sei [64];
    __shared__ float sal [64 * H];

    if (tid < H) sinv[tid] = 1.f / (den[d * H + tid] + 1e-16f);

    float4 acc = make_float4(0.f, 0.f, 0.f, 0.f);
    const int b0 = rowptr[d], b1 = rowptr[d + 1];

    for (int base = b0; base < b1; base += 64) {
        const int cnt = min(64, b1 - base);
        __syncthreads();
        if (tid < cnt) {
            const int e = csr[base + tid];
            sei[tid]  = e;
            ssrc[tid] = src[e];
        }
        __syncthreads();
        for (int idx = tid; idx < cnt * H; idx += NT) {
            const int i = idx / H, hh = idx - i * H;
            sal[idx] = exb[(size_t)sei[i] * H + hh] * sinv[hh];
        }
        __syncthreads();
#pragma unroll 4
        for (int i = 0; i < cnt; i++) {
            const float4 v = *(const float4*)&hw[(size_t)ssrc[i] * TOT + c4];
            const float  al = sal[i * H + h];
            acc.x += v.x * al;
            acc.y += v.y * al;
            acc.z += v.z * al;
            acc.w += v.w * al;
        }
    }

    const float4 bb = *(const float4*)&bias[c4];
    acc.x += bb.x; acc.y += bb.y; acc.z += bb.z; acc.w += bb.w;
    if (RELU) {
        acc.x = fmaxf(acc.x, 0.f);
        acc.y = fmaxf(acc.y, 0.f);
        acc.z = fmaxf(acc.z, 0.f);
        acc.w = fmaxf(acc.w, 0.f);
    }
    *(float4*)&out[(size_t)d * TOT + c4] = acc;
}

// ---------------------------------------------------------------------------
extern "C" void kernel_launch(void* const* d_in, const int* in_sizes, int n_in,
                              void* d_out, int out_size)
{
    (void)in_sizes; (void)n_in; (void)out_size;

    const float* x   = (const float*)d_in[0];
    const int*   ei  = (const int*)  d_in[1];
    const float* ew  = (const float*)d_in[2];
    const float* W1  = (const float*)d_in[3];
    const float* as1 = (const float*)d_in[4];
    const float* ad1 = (const float*)d_in[5];
    const float* We1 = (const float*)d_in[6];
    const float* ae1 = (const float*)d_in[7];
    const float* b1  = (const float*)d_in[8];
    const float* W2  = (const float*)d_in[9];
    const float* as2 = (const float*)d_in[10];
    const float* ad2 = (const float*)d_in[11];
    const float* We2 = (const float*)d_in[12];
    const float* ae2 = (const float*)d_in[13];
    const float* b2  = (const float*)d_in[14];
    const float* W3  = (const float*)d_in[15];
    const float* as3 = (const float*)d_in[16];
    const float* ad3 = (const float*)d_in[17];
    const float* We3 = (const float*)d_in[18];
    const float* ae3 = (const float*)d_in[19];
    const float* b3  = (const float*)d_in[20];
    const int* src = ei;
    const int* dst = ei + EE;
    float* outp = (float*)d_out;

    float *hw, *hin, *asrc, *adst, *amax, *den, *exb, *ce;
    int *deg, *rowptr, *cursor, *csr;
    cudaGetSymbolAddress((void**)&hw,     g_hw);
    cudaGetSymbolAddress((void**)&hin,    g_hin);
    cudaGetSymbolAddress((void**)&asrc,   g_asrc);
    cudaGetSymbolAddress((void**)&adst,   g_adst);
    cudaGetSymbolAddress((void**)&amax,   g_amax);
    cudaGetSymbolAddress((void**)&den,    g_den);
    cudaGetSymbolAddress((void**)&exb,    g_ex);
    cudaGetSymbolAddress((void**)&ce,     g_ce);
    cudaGetSymbolAddress((void**)&deg,    g_deg);
    cudaGetSymbolAddress((void**)&rowptr, g_rowptr);
    cudaGetSymbolAddress((void**)&cursor, g_cursor);
    cudaGetSymbolAddress((void**)&csr,    g_csr);

    const int MB = (NN + 127) / 128;

    // ---- CSR build (dst-indexed, reused by all layers) ----
    zero_deg<<<(NN + 255) / 256, 256>>>(deg);
    count_deg<<<(EE + 255) / 256, 256>>>(dst, deg);
    scan_rowptr<<<1, 1024>>>(deg, rowptr);
    init_cursor<<<(NN + 255) / 256, 256>>>(rowptr, cursor);
    scatter_csr<<<(EE + 255) / 256, 256>>>(dst, cursor, csr);

    // ---------------- Layer 1 (in=SEQ via transposed x, out=HC) ------------
    gemm_bf3<true><<<dim3(HC / 128, MB), 256>>>(x, W1, hw, NN, SEQL, HC, NN);
    node_dot<<<(NN * NH * 32 + 255) / 256, 256>>>(hw, as1, ad1, asrc, adst, HIDC, NH);
    ce_kernel<<<1, NH>>>(We1, ae1, ce, HIDC, NH);
    init_stats<<<(NN * NH + 255) / 256, 256>>>(amax, den, NN * NH);
    edge_logits<<<(EE * NH + 255) / 256, 256>>>(src, dst, ew, asrc, adst, ce, exb, amax, NH);
    edge_exp<<<(EE * NH + 255) / 256, 256>>>(dst, exb, amax, den, NH);
    agg_csr<HIDC, NH, true><<<NN, HC / 4>>>(rowptr, csr, src, hw, exb, den, b1, hin);

    // ---------------- Layer 2 (in=HC, out=HC) ------------------------------
    gemm_bf3<false><<<dim3(HC / 128, MB), 256>>>(hin, W2, hw, NN, HC, HC, HC);
    node_dot<<<(NN * NH * 32 + 255) / 256, 256>>>(hw, as2, ad2, asrc, adst, HIDC, NH);
    ce_kernel<<<1, NH>>>(We2, ae2, ce, HIDC, NH);
    init_stats<<<(NN * NH + 255) / 256, 256>>>(amax, den, NN * NH);
    edge_logits<<<(EE * NH + 255) / 256, 256>>>(src, dst, ew, asrc, adst, ce, exb, amax, NH);
    edge_exp<<<(EE * NH + 255) / 256, 256>>>(dst, exb, amax, den, NH);
    agg_csr<HIDC, NH, true><<<NN, HC / 4>>>(rowptr, csr, src, hw, exb, den, b2, hin);

    // ---------------- Layer 3 (in=HC, out=OUT, heads=1, no concat) ---------
    gemm_bf3<false><<<dim3(OUTC / 128, MB), 256>>>(hin, W3, hw, NN, HC, OUTC, HC);
    node_dot<<<(NN * 32 + 255) / 256, 256>>>(hw, as3, ad3, asrc, adst, OUTC, 1);
    ce_kernel<<<1, 1>>>(We3, ae3, ce, OUTC, 1);
    init_stats<<<(NN + 255) / 256, 256>>>(amax, den, NN);
    edge_logits<<<(EE + 255) / 256, 256>>>(src, dst, ew, asrc, adst, ce, exb, amax, 1);
    edge_exp<<<(EE + 255) / 256, 256>>>(dst, exb, amax, den, 1);
    agg_csr<OUTC, 1, false><<<NN, OUTC / 4>>>(rowptr, csr, src, hw, exb, den, b3, outp);
}